// round 9
// baseline (speedup 1.0000x reference)
#include <cuda_runtime.h>
#include <math.h>

#define N_NODES   20000
#define N_EDGES   320000
#define MUL0      64
#define NODE_DIM  240          // 64 + 3*32 + 5*16
#define NUM_BASIS 16
#define NCH       112          // 64 + 32 + 16 fused channels
#define NSTAT     144          // 9 * 16 sufficient statistics per node
#define INV_SQRT_MAXAT 0.0916698497028211f   // 1/sqrt(119)

// Fused projection matrices: M[b][ch] includes one_scalar and 1/sqrt(64)
__device__ float g_M[NUM_BASIS * NCH];
// Per-node sufficient statistics: G[n][j][b] = sum_e sh_e[j] * rbf_e[b]
__device__ float g_stats[(size_t)N_NODES * NSTAT];

// ---------------------------------------------------------------------------
// K1: zero stats (grid-stride, FULL chip) + precompute fused M (first 1792 warps)
// ---------------------------------------------------------------------------
__global__ void __launch_bounds__(256)
setup_kernel(const float* __restrict__ W_rbf,
             const float* __restrict__ w_expand,
             const float* __restrict__ b_expand,
             const float* __restrict__ Wp0,
             const float* __restrict__ Wp1,
             const float* __restrict__ Wp2)
{
    int tid = blockIdx.x * blockDim.x + threadIdx.x;

    // zero stats as float4
    const int n4 = N_NODES * NSTAT / 4;
    float4 z = make_float4(0.f, 0.f, 0.f, 0.f);
    for (int i = tid; i < n4; i += gridDim.x * blockDim.x)
        ((float4*)g_stats)[i] = z;

    // fused M: one warp per output element
    int w    = tid >> 5;
    int lane = threadIdx.x & 31;
    if (w >= NUM_BASIS * NCH) return;
    int b  = w / NCH;
    int ch = w % NCH;

    int   roff;
    const float* Wp;
    int   K, d;
    if (ch < 64)       { roff = 0;   Wp = Wp0; K = 64; d = ch; }
    else if (ch < 96)  { roff = 64;  Wp = Wp1; K = 32; d = ch - 64; }
    else               { roff = 128; Wp = Wp2; K = 16; d = ch - 96; }

    float acc = 0.f;
    #pragma unroll
    for (int h = 0; h < 2; ++h) {
        int c = lane + 32 * h;
        acc = fmaf(W_rbf[b * 192 + roff + c] * (w_expand[c] + b_expand[c]),
                   Wp[c * K + d], acc);
    }
    #pragma unroll
    for (int off = 16; off > 0; off >>= 1)
        acc += __shfl_xor_sync(0xffffffffu, acc, off);

    if (lane == 0) g_M[b * NCH + ch] = acc * 0.125f;   // * 1/sqrt(64)
}

// ---------------------------------------------------------------------------
// Vectorized L2 reduction
// ---------------------------------------------------------------------------
__device__ __forceinline__ void red_add_v4(float* addr, float a, float b, float c, float d)
{
    asm volatile("red.global.add.v4.f32 [%0], {%1,%2,%3,%4};"
                 :: "l"(addr), "f"(a), "f"(b), "f"(c), "f"(d) : "memory");
}

// ---------------------------------------------------------------------------
// K2: per-edge rbf + rsh outputs, warp-cooperative coalesced stats flush
// ---------------------------------------------------------------------------
#define EK_THREADS 128
#define ROWSTRIDE  28          // floats; 112B, 16B-aligned

__global__ void __launch_bounds__(EK_THREADS)
edge_kernel(const float* __restrict__ pos,
            const int*   __restrict__ edge_index,
            float*       __restrict__ rbf_out,
            float*       __restrict__ rsh_out)
{
    __shared__ float sbuf[4][32][ROWSTRIDE];   // [warp][edge][0:16 rbf |16:25 sh]
    __shared__ int   sdst[4][32];

    int tid  = threadIdx.x;
    int warp = tid >> 5;
    int lane = tid & 31;
    int e = blockIdx.x * EK_THREADS + tid;

    bool in_range = (e < N_EDGES);
    bool active = false;
    float* mybuf = sbuf[warp][lane];

    if (in_range) {
        int src = edge_index[e];
        int dst = edge_index[N_EDGES + e];
        sdst[warp][lane] = dst;

        const float* Ps = pos + 3 * src;
        const float* Pd = pos + 3 * dst;
        // reference permutes pos columns to [1,2,0] before differencing
        float vx = Pd[1] - Ps[1];
        float vy = Pd[2] - Ps[2];
        float vz = Pd[0] - Ps[0];

        float d2   = vx * vx + vy * vy + vz * vz;
        float dist = sqrtf(d2);
        float dcl  = fmaxf(dist, 1e-8f);
        float uinv = 1.0f / dcl;
        float x = vx * uinv, y = vy * uinv, z = vz * uinv;

        const float s3  = 1.7320508075688772f;
        const float s5  = 2.23606797749979f;
        const float s15 = 3.872983346207417f;

        float sh[9];
        sh[0] = 1.f;
        sh[1] = s3 * x;
        sh[2] = s3 * y;
        sh[3] = s3 * z;
        sh[4] = s15 * x * z;
        sh[5] = s15 * x * y;
        sh[6] = s5 * (y * y - 0.5f * (x * x + z * z));
        sh[7] = s15 * y * z;
        sh[8] = 0.5f * s15 * (z * z - x * x);

        {
            float* ro = rsh_out + (size_t)e * 9;
            #pragma unroll
            for (int i = 0; i < 9; ++i) ro[i] = sh[i];
        }

        float rbf[16];
        active = (dcl < 5.0f);
        if (active) {
            float X  = dcl * 0.2f;
            float X2 = X * X;
            float X5 = X2 * X2 * X;
            float fc = 1.0f + X5 * (-21.0f + X * (35.0f - 15.0f * X));
            float theta = 3.14159265358979323846f * X;
            // precise sinf/cosf: MUFU fast path destroys tiny theta
            // (self-loop edges, d ~ 1e-8) via fixed-point argument granularity
            float s1 = sinf(theta), c1 = cosf(theta);
            float two  = 2.0f * c1;
            float pref = 0.6324555320336759f * uinv * fc;   // sqrt(2/5)/d * fc
            float sp = 0.f, s = s1;
            #pragma unroll
            for (int n = 0; n < 16; ++n) {
                rbf[n] = pref * s;
                float sn = two * s - sp;
                sp = s; s = sn;
            }
        } else {
            #pragma unroll
            for (int n = 0; n < 16; ++n) rbf[n] = 0.f;
        }

        {
            float4* ro = (float4*)(rbf_out + (size_t)e * 16);
            #pragma unroll
            for (int q = 0; q < 4; ++q)
                ro[q] = make_float4(rbf[4*q], rbf[4*q+1], rbf[4*q+2], rbf[4*q+3]);
        }

        #pragma unroll
        for (int i = 0; i < 16; ++i) mybuf[i] = rbf[i];
        #pragma unroll
        for (int j = 0; j < 9; ++j)  mybuf[16 + j] = sh[j];
    }

    unsigned act = __ballot_sync(0xffffffffu, active);
    __syncwarp();

    // warp-cooperative flush: one edge at a time, coalesced red.v4
    while (act) {
        int k = __ffs(act) - 1;
        act &= act - 1;
        const float* eb = sbuf[warp][k];
        float* S = g_stats + (size_t)sdst[warp][k] * NSTAT;

        float  sj = eb[16 + (lane >> 2)];
        float4 r  = *(const float4*)(eb + ((lane & 3) << 2));
        red_add_v4(S + 4 * lane, sj * r.x, sj * r.y, sj * r.z, sj * r.w);

        if (lane < 4) {
            float  s8 = eb[24];
            float4 r2 = *(const float4*)(eb + (lane << 2));
            red_add_v4(S + 128 + 4 * lane, s8 * r2.x, s8 * r2.y, s8 * r2.z, s8 * r2.w);
        }
    }
}

// ---------------------------------------------------------------------------
// K3: node projection, M in registers, ONE column per thread.
//     256 threads/block (240 working), 32 nodes/block, 8 nodes per sync round.
//     Warp-aligned task map so G-row offset (goff) is uniform per warp
//     (pure LDS broadcast):
//       t in [0,64)    path0: goff=0,        mcol=t,       ch=t
//       t in [64,160)  path1: m=(t-64)>>5, d=(t-64)&31
//                              goff=(1+m)*16, mcol=64+d,    ch=64+3d+m
//       t in [160,240) path2: m=(t-160)>>4, d=(t-160)&15
//                              goff=(4+m)*16, mcol=96+d,    ch=160+5d+m
// ---------------------------------------------------------------------------
#define NB              8      // nodes per sync round
#define NODES_PER_BLOCK 32

__global__ void __launch_bounds__(256)
node_kernel(const int*   __restrict__ at_no,
            const float* __restrict__ W_atom,
            const float* __restrict__ b_atom,
            float*       __restrict__ node_emb)
{
    __shared__ __align__(16) float sG[NB * NSTAT];   // 8 x 144 = 4608 B

    int t = threadIdx.x;
    bool tvalid = (t < 240);

    int goff = 0, mcol = 0, ch = 0;
    bool is_p0 = (t < 64);
    if (t < 64) {
        goff = 0;            mcol = t;        ch = t;
    } else if (t < 160) {
        int p = t - 64, m = p >> 5, d = p & 31;
        goff = (1 + m) * 16; mcol = 64 + d;   ch = 64 + 3 * d + m;
    } else if (t < 240) {
        int p = t - 160, m = p >> 4, d = p & 15;
        goff = (4 + m) * 16; mcol = 96 + d;   ch = 160 + 5 * d + m;
    }

    // preload this thread's M column into registers
    float mr[16];
    if (tvalid) {
        #pragma unroll
        for (int b = 0; b < 16; ++b)
            mr[b] = g_M[b * NCH + mcol];
    }

    int nbase0 = blockIdx.x * NODES_PER_BLOCK;

    #pragma unroll
    for (int it = 0; it < NODES_PER_BLOCK / NB; ++it) {
        int nbase = nbase0 + it * NB;

        __syncthreads();   // previous round's sG fully consumed
        {
            // NB*NSTAT/4 = 288 float4 over 256 threads
            const float4* Sp = (const float4*)(g_stats + (size_t)nbase * NSTAT);
            float4* Dp = (float4*)sG;
            Dp[t] = Sp[t];
            if (t < 32) Dp[256 + t] = Sp[256 + t];
        }
        __syncthreads();

        if (tvalid) {
            #pragma unroll
            for (int k = 0; k < NB; ++k) {
                int n = nbase + k;
                const float* G = sG + k * NSTAT + goff;
                float a = 0.f;
                #pragma unroll
                for (int b = 0; b < 16; ++b)
                    a = fmaf(G[b], mr[b], a);
                float* nrow = node_emb + (size_t)n * NODE_DIM;
                if (is_p0) {
                    int an = at_no[n];
                    a += fmaf(W_atom[an * MUL0 + ch], INV_SQRT_MAXAT, b_atom[ch]);
                }
                nrow[ch] = a;
            }
        }
    }
}

// ---------------------------------------------------------------------------
// Launch
// ---------------------------------------------------------------------------
extern "C" void kernel_launch(void* const* d_in, const int* in_sizes, int n_in,
                              void* d_out, int out_size)
{
    const int*   at_no      = (const int*)  d_in[0];
    const float* pos        = (const float*)d_in[1];
    const int*   edge_index = (const int*)  d_in[2];
    const float* W_atom     = (const float*)d_in[3];
    const float* b_atom     = (const float*)d_in[4];
    const float* w_expand   = (const float*)d_in[5];
    const float* b_expand   = (const float*)d_in[6];
    const float* W_rbf      = (const float*)d_in[7];
    const float* Wp0        = (const float*)d_in[8];
    const float* Wp1        = (const float*)d_in[9];
    const float* Wp2        = (const float*)d_in[10];

    float* out      = (float*)d_out;
    float* node_emb = out;                                   // 20000*240
    float* rbf_out  = out + (size_t)N_NODES * NODE_DIM;      // 320000*16
    float* rsh_out  = rbf_out + (size_t)N_EDGES * NUM_BASIS; // 320000*9

    setup_kernel<<<1480, 256>>>(W_rbf, w_expand, b_expand, Wp0, Wp1, Wp2);
    edge_kernel<<<(N_EDGES + EK_THREADS - 1) / EK_THREADS, EK_THREADS>>>(
        pos, edge_index, rbf_out, rsh_out);
    node_kernel<<<N_NODES / NODES_PER_BLOCK, 256>>>(at_no, W_atom, b_atom, node_emb);
}